// round 16
// baseline (speedup 1.0000x reference)
#include <cuda_runtime.h>
#include <cuda_bf16.h>
#include <stdint.h>
#include <math.h>

#define NB 2
#define BB 4
#define TT 2048
#define DD 128
#define HH 4
#define DK 32
#define ROWS (BB*TT)          // 8192
#define LN_EPS 1e-3f

// -------------------- scratch (device globals; no allocs allowed) ------------
__device__ float g_pe [TT*DD];
// packed activations: [row][kc(8)*4+lr(4)] uint4 = {hi(dp),hi(dp+4),lo(dp),lo(dp+4)}
__device__ uint4 g_hnp [ROWS*32];
__device__ uint4 g_ctxp[ROWS*32];
// packed Q/K: [bh=16][t=2048][kc(2)*4+lr(4)]
__device__ uint4 g_qp[32768*8];
__device__ uint4 g_kp[32768*8];
// packed V: [bh=16][tile(32)][d(32)][kc(4)*4+lr(4)] over key-pairs
__device__ uint4 g_vp[16*32*32*16];
// packed W: [matrix(12)][n(128)][kc(8)*4+lr(4)]
__device__ uint4 g_wp[12*128*32];

// -------------------- split-bf16 helpers ---------------------------------------
__device__ __forceinline__ uint32_t pk_bf2(float a, float b) {
    __nv_bfloat162 t = __floats2bfloat162_rn(a, b);
    return *reinterpret_cast<uint32_t*>(&t);
}
__device__ __forceinline__ void split2(float a, float b, uint32_t& h, uint32_t& l) {
    float ah = __bfloat162float(__float2bfloat16(a));
    float bh = __bfloat162float(__float2bfloat16(b));
    h = pk_bf2(ah, bh);
    l = pk_bf2(a - ah, b - bh);
}
__device__ __forceinline__ float2 unsplit(uint32_t h, uint32_t l) {
    __nv_bfloat162 hb = *reinterpret_cast<__nv_bfloat162*>(&h);
    __nv_bfloat162 lb = *reinterpret_cast<__nv_bfloat162*>(&l);
    return make_float2(__bfloat162float(hb.x) + __bfloat162float(lb.x),
                       __bfloat162float(hb.y) + __bfloat162float(lb.y));
}
__device__ __forceinline__ void mma16816(float c[4], const uint32_t a[4], const uint32_t b[2]) {
    asm volatile(
        "mma.sync.aligned.m16n8k16.row.col.f32.bf16.bf16.f32 "
        "{%0,%1,%2,%3}, {%4,%5,%6,%7}, {%8,%9}, {%0,%1,%2,%3};\n"
        : "+f"(c[0]), "+f"(c[1]), "+f"(c[2]), "+f"(c[3])
        : "r"(a[0]), "r"(a[1]), "r"(a[2]), "r"(a[3]), "r"(b[0]), "r"(b[1]));
}

// -------------------- positional encoding -------------------------------------
__global__ void pe_kernel(float* __restrict__ pe) {
    int i = blockIdx.x;
    double f = exp(-((double)(2 * i) / 128.0) * 9.210340371976184);
    const double TWO_PI = 6.283185307179586;
    const double INV_TWO_PI = 0.15915494309189535;
    for (int t = threadIdx.x; t < TT; t += blockDim.x) {
        double ang = (double)t * f;
        double r = ang - TWO_PI * floor(ang * INV_TWO_PI);
        float rf = (float)r;
        pe[t * DD + i] = (i & 1) ? cosf(rf) : sinf(rf);
    }
}

// -------------------- fused addpos + first LayerNorm -> packed hn ----------------
__global__ void addpos_ln_kernel(const float* __restrict__ in, const float* __restrict__ pe,
                                 const float* __restrict__ g, const float* __restrict__ b,
                                 uint4* __restrict__ Cp) {
    int row  = blockIdx.x * 8 + (threadIdx.x >> 5);
    int j    = threadIdx.x & 31;
    int dp   = ((j >> 2) << 3) + (j & 3);
    int d0   = 2 * dp;
    int t = row & (TT - 1);
    const float* inr = in + (size_t)row * 128;
    const float* per = pe + (size_t)t * 128;
    float2 xa = *(const float2*)&inr[d0];
    float2 xb = *(const float2*)&inr[d0 + 8];
    float2 pa = *(const float2*)&per[d0];
    float2 pb = *(const float2*)&per[d0 + 8];
    xa.x += pa.x; xa.y += pa.y; xb.x += pb.x; xb.y += pb.y;
    float s = xa.x + xa.y + xb.x + xb.y;
    #pragma unroll
    for (int o = 16; o > 0; o >>= 1) s += __shfl_xor_sync(0xffffffff, s, o);
    float mu = s * (1.0f / 128.0f);
    float dx0 = xa.x - mu, dx1 = xa.y - mu, dx2 = xb.x - mu, dx3 = xb.y - mu;
    float sq = dx0*dx0 + dx1*dx1 + dx2*dx2 + dx3*dx3;
    #pragma unroll
    for (int o = 16; o > 0; o >>= 1) sq += __shfl_xor_sync(0xffffffff, sq, o);
    float var = sq * (1.0f / 128.0f);
    float r = rsqrtf(var + LN_EPS);
    float2 ga = *(const float2*)&g[d0];
    float2 gb = *(const float2*)&g[d0 + 8];
    float2 ba = *(const float2*)&b[d0];
    float2 bb = *(const float2*)&b[d0 + 8];
    float y0 = ga.x * dx0 * r + ba.x;
    float y1 = ga.y * dx1 * r + ba.y;
    float y2 = gb.x * dx2 * r + bb.x;
    float y3 = gb.y * dx3 * r + bb.y;
    uint32_t h0, l0, h1, l1;
    split2(y0, y1, h0, l0);
    split2(y2, y3, h1, l1);
    Cp[(size_t)row * 32 + j] = make_uint4(h0, h1, l0, l1);
}

// -------------------- weight pre-split into packed uint4 -------------------------
__global__ void wsplit_kernel(const float* __restrict__ Wq, const float* __restrict__ Wk,
                              const float* __restrict__ Wv, const float* __restrict__ Wo,
                              const float* __restrict__ W1, const float* __restrict__ W2,
                              uint4* __restrict__ wp) {
    const float* Ws[6] = {Wq, Wk, Wv, Wo, W1, W2};
    int fam = blockIdx.y;
    int idx = blockIdx.x * 256 + threadIdx.x;   // 0..8191 = NB*128*32
    int layer = idx >> 12;
    int rem = idx & 4095;
    int n = rem >> 5;
    int j = rem & 31;
    int kc = j >> 2, lr = j & 3;
    int kp1 = kc * 8 + lr, kp2 = kp1 + 4;
    const float* Wm = Ws[fam] + layer * 128 * 128;
    uint32_t h1, l1, h2, l2;
    split2(Wm[(2 * kp1) * 128 + n], Wm[(2 * kp1 + 1) * 128 + n], h1, l1);
    split2(Wm[(2 * kp2) * 128 + n], Wm[(2 * kp2 + 1) * 128 + n], h2, l2);
    wp[((fam * NB + layer) * 128 + n) * 32 + j] = make_uint4(h1, h2, l1, l2);
}

// ==================== fused QKV (N=64 tile) =======================================
__global__ __launch_bounds__(256) void qkv64_kernel(
        const uint4* __restrict__ Ap,
        const uint4* __restrict__ Wpq, const float* __restrict__ bq,
        const uint4* __restrict__ Wpk, const float* __restrict__ bk,
        const uint4* __restrict__ Wpv, const float* __restrict__ bv,
        uint4* __restrict__ qp, uint4* __restrict__ kp, uint4* __restrict__ vp) {
    __shared__ __align__(16) float Vt[64 * 65];   // V transpose scratch only
    int tid = threadIdx.x;
    int w = tid >> 5, lane = tid & 31;
    int lq = lane >> 2, lr = lane & 3;
    int rg = w >> 1, cg = w & 1;
    int m0 = (blockIdx.x >> 1) * 64;
    int n0 = (blockIdx.x & 1) * 64;
    int sel = blockIdx.y;
    const float QSCL = 0.17677669529663687f * 1.4426950408889634f;
    const uint4* Wp = (sel == 0) ? Wpq : (sel == 1) ? Wpk : Wpv;
    const float* bias = (sel == 0) ? bq : (sel == 1) ? bk : bv;
    float scl = (sel == 0) ? QSCL : 1.0f;
    const uint4* Wb = Wp + (size_t)n0 * 32;

    int mrow = m0 + rg * 16 + lq;
    const uint4* A0 = Ap + (size_t)mrow * 32;
    const uint4* A1 = Ap + (size_t)(mrow + 8) * 32;
    float acc[4][4] = {};

    #pragma unroll
    for (int kc = 0; kc < 8; kc++) {
        uint4 a0 = A0[kc * 4 + lr];
        uint4 a1 = A1[kc * 4 + lr];
        uint32_t ah[4] = { a0.x, a1.x, a0.y, a1.y };
        uint32_t al[4] = { a0.z, a1.z, a0.w, a1.w };
        #pragma unroll
        for (int nt = 0; nt < 4; nt++) {
            int n = cg * 32 + nt * 8 + lq;
            uint4 wv = Wb[(size_t)n * 32 + kc * 4 + lr];
            uint32_t bh2[2] = { wv.x, wv.y };
            uint32_t bl2[2] = { wv.z, wv.w };
            mma16816(acc[nt], ah, bh2);
            mma16816(acc[nt], ah, bl2);
            mma16816(acc[nt], al, bh2);
        }
    }

    if (sel == 2) {
        int k0 = rg * 16 + lq;
        #pragma unroll
        for (int nt = 0; nt < 4; nt++) {
            int dc = cg * 32 + nt * 8 + 2 * lr;
            int n = n0 + dc;
            float2 bv2 = *(const float2*)&bias[n];
            Vt[dc * 65 + k0]           = acc[nt][0] + bv2.x;
            Vt[(dc + 1) * 65 + k0]     = acc[nt][1] + bv2.y;
            Vt[dc * 65 + k0 + 8]       = acc[nt][2] + bv2.x;
            Vt[(dc + 1) * 65 + k0 + 8] = acc[nt][3] + bv2.y;
        }
        __syncthreads();
        int b = m0 >> 11, tile = (m0 & 2047) >> 6;
        #pragma unroll
        for (int i = 0; i < 4; i++) {
            int idx = tid + i * 256;
            int dc = idx >> 4, j = idx & 15;
            int kc2 = j >> 2, lr2 = j & 3;
            int kpi = kc2 * 8 + lr2;
            float v0 = Vt[dc * 65 + 2 * kpi];
            float v1 = Vt[dc * 65 + 2 * kpi + 1];
            float v2 = Vt[dc * 65 + 2 * kpi + 8];
            float v3 = Vt[dc * 65 + 2 * kpi + 9];
            uint32_t h1, l1, h2, l2;
            split2(v0, v1, h1, l1);
            split2(v2, v3, h2, l2);
            int bh = (b << 2) + (n0 >> 5) + (dc >> 5);
            int d = dc & 31;
            vp[(((size_t)bh * 32 + tile) * 32 + d) * 16 + j] = make_uint4(h1, h2, l1, l2);
        }
        return;
    }

    uint4* Cp = (sel == 0) ? qp : kp;
    int hh = (n0 >> 5) + cg;
    int b0i = mrow >> 11, t0i = mrow & 2047;
    int b1i = (mrow + 8) >> 11, t1i = (mrow + 8) & 2047;
    uint32_t hi0[4], lo0r[4], hi1[4], lo1r[4];
    #pragma unroll
    for (int nt = 0; nt < 4; nt++) {
        int n = n0 + cg * 32 + nt * 8 + 2 * lr;
        float2 bv2 = *(const float2*)&bias[n];
        split2((acc[nt][0] + bv2.x) * scl, (acc[nt][1] + bv2.y) * scl, hi0[nt], lo0r[nt]);
        split2((acc[nt][2] + bv2.x) * scl, (acc[nt][3] + bv2.y) * scl, hi1[nt], lo1r[nt]);
    }
    size_t base0 = ((size_t)((b0i << 2) + hh) * 2048 + t0i) * 8;
    size_t base1 = ((size_t)((b1i << 2) + hh) * 2048 + t1i) * 8;
    Cp[base0 + lr]     = make_uint4(hi0[0], hi0[1], lo0r[0], lo0r[1]);
    Cp[base0 + 4 + lr] = make_uint4(hi0[2], hi0[3], lo0r[2], lo0r[3]);
    Cp[base1 + lr]     = make_uint4(hi1[0], hi1[1], lo1r[0], lo1r[1]);
    Cp[base1 + 4 + lr] = make_uint4(hi1[2], hi1[3], lo1r[2], lo1r[3]);
}

// ==================== Wo GEMM + LN: M=16, 128 threads, grid 512 ===================
__global__ __launch_bounds__(128) void gemm_ln_kernel(
        const uint4* __restrict__ Ap, const uint4* __restrict__ Wp,
        const float* __restrict__ bias,
        const float* __restrict__ lng, const float* __restrict__ lnb,
        uint4* __restrict__ Cp) {
    __shared__ float ssum[16][4];
    __shared__ float ssq[16][4];
    int tid = threadIdx.x;
    int w = tid >> 5, lane = tid & 31;
    int lq = lane >> 2, lr = lane & 3;
    int cg = w;
    int m0 = blockIdx.x * 16;

    int mrow = m0 + lq;
    const uint4* A0 = Ap + (size_t)mrow * 32;
    const uint4* A1 = Ap + (size_t)(mrow + 8) * 32;
    float acc[4][4] = {};

    #pragma unroll
    for (int kc = 0; kc < 8; kc++) {
        uint4 a0 = A0[kc * 4 + lr];
        uint4 a1 = A1[kc * 4 + lr];
        uint32_t ah[4] = { a0.x, a1.x, a0.y, a1.y };
        uint32_t al[4] = { a0.z, a1.z, a0.w, a1.w };
        #pragma unroll
        for (int nt = 0; nt < 4; nt++) {
            int n = cg * 32 + nt * 8 + lq;
            uint4 wv = Wp[(size_t)n * 32 + kc * 4 + lr];
            uint32_t bh2[2] = { wv.x, wv.y };
            uint32_t bl2[2] = { wv.z, wv.w };
            mma16816(acc[nt], ah, bh2);
            mma16816(acc[nt], ah, bl2);
            mma16816(acc[nt], al, bh2);
        }
    }

    float xs[4][4];
    #pragma unroll
    for (int nt = 0; nt < 4; nt++) {
        int n = cg * 32 + nt * 8 + 2 * lr;
        float2 bv = *(const float2*)&bias[n];
        xs[nt][0] = acc[nt][0] + bv.x;
        xs[nt][1] = acc[nt][1] + bv.y;
        xs[nt][2] = acc[nt][2] + bv.x;
        xs[nt][3] = acc[nt][3] + bv.y;
    }
    float sA = 0, qA = 0, sB = 0, qB = 0;
    #pragma unroll
    for (int nt = 0; nt < 4; nt++) {
        sA += xs[nt][0] + xs[nt][1];
        qA += xs[nt][0]*xs[nt][0] + xs[nt][1]*xs[nt][1];
        sB += xs[nt][2] + xs[nt][3];
        qB += xs[nt][2]*xs[nt][2] + xs[nt][3]*xs[nt][3];
    }
    #pragma unroll
    for (int o2 = 1; o2 < 4; o2 <<= 1) {
        sA += __shfl_xor_sync(0xffffffff, sA, o2);
        qA += __shfl_xor_sync(0xffffffff, qA, o2);
        sB += __shfl_xor_sync(0xffffffff, sB, o2);
        qB += __shfl_xor_sync(0xffffffff, qB, o2);
    }
    int ra = lq, rb = lq + 8;
    if (lr == 0) {
        ssum[ra][cg] = sA; ssq[ra][cg] = qA;
        ssum[rb][cg] = sB; ssq[rb][cg] = qB;
    }
    __syncthreads();
    float fsA = ssum[ra][0] + ssum[ra][1] + ssum[ra][2] + ssum[ra][3];
    float fqA = ssq[ra][0] + ssq[ra][1] + ssq[ra][2] + ssq[ra][3];
    float fsB = ssum[rb][0] + ssum[rb][1] + ssum[rb][2] + ssum[rb][3];
    float fqB = ssq[rb][0] + ssq[rb][1] + ssq[rb][2] + ssq[rb][3];
    float muA = fsA * (1.0f / 128.0f);
    float muB = fsB * (1.0f / 128.0f);
    float rA = rsqrtf(fqA * (1.0f / 128.0f) - muA * muA + LN_EPS);
    float rB = rsqrtf(fqB * (1.0f / 128.0f) - muB * muB + LN_EPS);
    uint32_t hA[4], lA[4], hB[4], lB[4];
    #pragma unroll
    for (int nt = 0; nt < 4; nt++) {
        int n = cg * 32 + nt * 8 + 2 * lr;
        float2 gv  = *(const float2*)&lng[n];
        float2 bv2 = *(const float2*)&lnb[n];
        split2(gv.x * (xs[nt][0] - muA) * rA + bv2.x,
               gv.y * (xs[nt][1] - muA) * rA + bv2.y, hA[nt], lA[nt]);
        split2(gv.x * (xs[nt][2] - muB) * rB + bv2.x,
               gv.y * (xs[nt][3] - muB) * rB + bv2.y, hB[nt], lB[nt]);
    }
    int jb = cg * 8 + lr;
    Cp[(size_t)mrow * 32 + jb]           = make_uint4(hA[0], hA[1], lA[0], lA[1]);
    Cp[(size_t)mrow * 32 + jb + 4]       = make_uint4(hA[2], hA[3], lA[2], lA[3]);
    Cp[(size_t)(mrow + 8) * 32 + jb]     = make_uint4(hB[0], hB[1], lB[0], lB[1]);
    Cp[(size_t)(mrow + 8) * 32 + jb + 4] = make_uint4(hB[2], hB[3], lB[2], lB[3]);
}

// ==================== fused FFN: M=16, 128 threads, grid 512 ======================
// MODE 6: -> packed Cp; MODE 7: -> fp32 C (final output)
template <int MODE>
__global__ __launch_bounds__(128) void ffn_kernel(
        const uint4* __restrict__ Ap,
        const uint4* __restrict__ Wp1, const float* __restrict__ b1,
        const uint4* __restrict__ Wp2, const float* __restrict__ b2,
        const float* __restrict__ lng, const float* __restrict__ lnb,
        float* __restrict__ C, uint4* __restrict__ Cp) {
    __shared__ __align__(16) uint4 Tp[16 * 36];   // packed tmp tile
    __shared__ float ssum[16][4];
    __shared__ float ssq[16][4];
    int tid = threadIdx.x;
    int w = tid >> 5, lane = tid & 31;
    int lq = lane >> 2, lr = lane & 3;
    int cg = w;
    int m0 = blockIdx.x * 16;
    int lrow0 = lq, lrow1 = lq + 8;
    int mrow = m0 + lrow0;

    // ---- stage 1: tmp = relu(hn @ W1 + b1) -> smem (split-packed) ----
    {
        const uint4* A0 = Ap + (size_t)mrow * 32;
        const uint4* A1 = A0 + 8 * 32;
        float acc[4][4] = {};
        #pragma unroll
        for (int kc = 0; kc < 8; kc++) {
            uint4 a0 = A0[kc * 4 + lr];
            uint4 a1 = A1[kc * 4 + lr];
            uint32_t ah[4] = { a0.x, a1.x, a0.y, a1.y };
            uint32_t al[4] = { a0.z, a1.z, a0.w, a1.w };
            #pragma unroll
            for (int nt = 0; nt < 4; nt++) {
                int n = cg * 32 + nt * 8 + lq;
                uint4 wv = Wp1[(size_t)n * 32 + kc * 4 + lr];
                uint32_t bh2[2] = { wv.x, wv.y };
                uint32_t bl2[2] = { wv.z, wv.w };
                mma16816(acc[nt], ah, bh2);
                mma16816(acc[nt], ah, bl2);
                mma16816(acc[nt], al, bh2);
            }
        }
        uint32_t h0[4], l0a[4], h1a[4], l1a[4];
        #pragma unroll
        for (int nt = 0; nt < 4; nt++) {
            int n = cg * 32 + nt * 8 + 2 * lr;
            float2 bv = *(const float2*)&b1[n];
            split2(fmaxf(acc[nt][0] + bv.x, 0.f), fmaxf(acc[nt][1] + bv.y, 0.f), h0[nt], l0a[nt]);
            split2(fmaxf(acc[nt][2] + bv.x, 0.f), fmaxf(acc[nt][3] + bv.y, 0.f), h1a[nt], l1a[nt]);
        }
        int jb = cg * 8 + lr;
        Tp[lrow0 * 36 + jb]     = make_uint4(h0[0], h0[1], l0a[0], l0a[1]);
        Tp[lrow0 * 36 + jb + 4] = make_uint4(h0[2], h0[3], l0a[2], l0a[3]);
        Tp[lrow1 * 36 + jb]     = make_uint4(h1a[0], h1a[1], l1a[0], l1a[1]);
        Tp[lrow1 * 36 + jb + 4] = make_uint4(h1a[2], h1a[3], l1a[2], l1a[3]);
    }
    __syncthreads();

    // ---- stage 2: y = LN(tmp @ W2 + b2 + hn) ----
    float acc[4][4] = {};
    #pragma unroll
    for (int kc = 0; kc < 8; kc++) {
        uint4 a0 = Tp[lrow0 * 36 + kc * 4 + lr];
        uint4 a1 = Tp[lrow1 * 36 + kc * 4 + lr];
        uint32_t ah[4] = { a0.x, a1.x, a0.y, a1.y };
        uint32_t al[4] = { a0.z, a1.z, a0.w, a1.w };
        #pragma unroll
        for (int nt = 0; nt < 4; nt++) {
            int n = cg * 32 + nt * 8 + lq;
            uint4 wv = Wp2[(size_t)n * 32 + kc * 4 + lr];
            uint32_t bh2[2] = { wv.x, wv.y };
            uint32_t bl2[2] = { wv.z, wv.w };
            mma16816(acc[nt], ah, bh2);
            mma16816(acc[nt], ah, bl2);
            mma16816(acc[nt], al, bh2);
        }
    }

    float xs[4][4];
    {
        uint4 rA0 = Ap[(size_t)mrow * 32 + cg * 8 + lr];
        uint4 rA1 = Ap[(size_t)mrow * 32 + cg * 8 + 4 + lr];
        uint4 rB0 = Ap[(size_t)(mrow + 8) * 32 + cg * 8 + lr];
        uint4 rB1 = Ap[(size_t)(mrow + 8) * 32 + cg * 8 + 4 + lr];
        float2 r;
        r = unsplit(rA0.x, rA0.z); xs[0][0] = r.x; xs[0][1] = r.y;
        r = unsplit(rA0.y, rA0.w); xs[1][0] = r.x; xs[1][1] = r.y;
        r = unsplit(rA1.x, rA1.z); xs[2][0] = r.x; xs[2][1] = r.y;
        r = unsplit(rA1.y, rA1.w); xs[3][0] = r.x; xs[3][1] = r.y;
        r = unsplit(rB0.x, rB0.z); xs[0][2] = r.x; xs[0][3] = r.y;
        r = unsplit(rB0.y, rB0.w); xs[1][2] = r.x; xs[1][3] = r.y;
        r = unsplit(rB1.x, rB1.z); xs[2][2] = r.x; xs[2][3] = r.y;
        r = unsplit(rB1.y, rB1.w); xs[3][2] = r.x; xs[3][3] = r.y;
    }
    #pragma unroll
    for (int nt = 0; nt < 4; nt++) {
        int n = cg * 32 + nt * 8 + 2 * lr;
        float2 bv = *(const float2*)&b2[n];
        xs[nt][0] += acc[nt][0] + bv.x;
        xs[nt][1] += acc[nt][1] + bv.y;
        xs[nt][2] += acc[nt][2] + bv.x;
        xs[nt][3] += acc[nt][3] + bv.y;
    }
    float sA = 0, qA = 0, sB = 0, qB = 0;
    #pragma unroll
    for (int nt = 0; nt < 4; nt++) {
        sA += xs[nt][0] + xs[nt][1];
        qA += xs[nt][0]*xs[nt][0] + xs[nt][1]*xs[nt][1];
        sB += xs[nt][2] + xs[nt][3];
        qB += xs[nt][2]*xs[nt][2] + xs[nt][3]*xs[nt][3];
    }
    #pragma unroll
    for (int o2 = 1; o2 < 4; o2 <<= 1) {
        sA += __shfl_xor_sync(0xffffffff, sA, o2);
        qA += __shfl_xor_sync(0xffffffff, qA, o2);
        sB += __shfl_xor_sync(0xffffffff, sB, o2);
        qB += __shfl_xor_sync(0xffffffff, qB, o2);
    }
    int ra = lrow0, rb = lrow1;
    if (lr == 0) {
        ssum[ra][cg] = sA; ssq[ra][cg] = qA;
        ssum[rb][cg] = sB; ssq[rb][cg] = qB;
    }
    __syncthreads();
    float fsA = ssum[ra][0] + ssum[ra][1] + ssum[ra][2] + ssum[ra][3];
    float fqA = ssq[ra][0] + ssq[ra][1] + ssq[ra][2] + ssq[ra][3];
    float fsB = ssum[rb][0] + ssum[rb][1] + ssum[rb][2] + ssum[rb][3];
    float fqB = ssq[rb][0] + ssq[rb][1] + ssq[rb][2] + ssq[rb][3];
    float muA = fsA * (1.0f / 128.0f);
    float muB = fsB * (1.0f / 128.0f);
    float rA = rsqrtf(fqA * (1.0f / 128.0f) - muA * muA + LN_EPS);
    float rB = rsqrtf(fqB * (1.0f / 128.0f) - muB * muB + LN_EPS);
    float yA[4][2], yB[4][2];
    #pragma unroll
    for (int nt = 0; nt < 4; nt++) {
        int n = cg * 32 + nt * 8 + 2 * lr;
        float2 gv  = *(const float2*)&lng[n];
        float2 bv2 = *(const float2*)&lnb[n];
        yA[nt][0] = gv.x * (xs[nt][0] - muA) * rA + bv2.x;
        yA[nt][1] = gv.y * (xs[nt][1] - muA) * rA + bv2.y;
        yB[nt][0] = gv.x * (xs[nt][2] - muB) * rB + bv2.x;
        yB[nt][1] = gv.y * (xs[nt][3] - muB) * rB + bv2.y;
    }
    if (MODE == 7) {
        #pragma unroll
        for (int nt = 0; nt < 4; nt++) {
            int n = cg * 32 + nt * 8 + 2 * lr;
            *(float2*)&C[(size_t)mrow * 128 + n] = make_float2(yA[nt][0], yA[nt][1]);
            *(float2*)&C[(size_t)(mrow + 8) * 128 + n] = make_float2(yB[nt][0], yB[nt][1]);
        }
    } else {
        uint32_t hA[4], lA[4], hB[4], lB[4];
        #pragma unroll
        for (int nt = 0; nt < 4; nt++) {
            split2(yA[nt][0], yA[nt][1], hA[nt], lA[nt]);
            split2(yB[nt][0], yB[nt][1], hB[nt], lB[nt]);
        }
        int jb = cg * 8 + lr;
        Cp[(size_t)mrow * 32 + jb]           = make_uint4(hA[0], hA[1], lA[0], lA[1]);
        Cp[(size_t)mrow * 32 + jb + 4]       = make_uint4(hA[2], hA[3], lA[2], lA[3]);
        Cp[(size_t)(mrow + 8) * 32 + jb]     = make_uint4(hB[0], hB[1], lB[0], lB[1]);
        Cp[(size_t)(mrow + 8) * 32 + jb + 4] = make_uint4(hB[2], hB[3], lB[2], lB[3]);
    }
}

// -------------------- flash attention (packed uint4) -----------------------------
__global__ __launch_bounds__(256) void attn_kernel(
        const uint4* __restrict__ Qp, const uint4* __restrict__ Kp,
        const uint4* __restrict__ Vp, uint4* __restrict__ Cp) {
    __shared__ __align__(16) uint4 Ks[2][64 * 12];
    __shared__ __align__(16) uint4 Vs[2][32 * 20];

    int bid = blockIdx.x;
    int bh  = bid >> 4;
    int qc  = bid & 15;
    int q0  = qc * 128;
    int tid = threadIdx.x;
    int w    = tid >> 5;
    int lane = tid & 31;
    int lq   = lane >> 2;
    int lr   = lane & 3;
    int row0 = q0 + w * 16 + lq;

    const uint4* QpB = Qp + (size_t)bh * 2048 * 8;
    const uint4* KpB = Kp + (size_t)bh * 2048 * 8;
    const uint4* VpB = Vp + (size_t)bh * 32 * 512;

    uint32_t qh[2][4], ql[2][4];
    #pragma unroll
    for (int c2 = 0; c2 < 2; c2++) {
        uint4 a0 = QpB[(size_t)row0 * 8 + c2 * 4 + lr];
        uint4 a1 = QpB[(size_t)(row0 + 8) * 8 + c2 * 4 + lr];
        qh[c2][0] = a0.x; qh[c2][1] = a1.x; qh[c2][2] = a0.y; qh[c2][3] = a1.y;
        ql[c2][0] = a0.z; ql[c2][1] = a1.z; ql[c2][2] = a0.w; ql[c2][3] = a1.w;
    }

    float m0 = -1e30f, m1 = -1e30f, l0 = 0.f, l1 = 0.f;
    float o[4][4] = {};

    int kkey = tid >> 3, kj = tid & 7;
    int vd = tid >> 4, vj = tid & 15;
    uint4 kr[2], vr[2];
    kr[0] = KpB[(size_t)kkey * 8 + kj];
    kr[1] = KpB[(size_t)(kkey + 32) * 8 + kj];
    vr[0] = VpB[(size_t)vd * 16 + vj];
    vr[1] = VpB[(size_t)(vd + 16) * 16 + vj];

    for (int tile = 0; tile < 32; tile++) {
        int cur = tile & 1;
        Ks[cur][kkey * 12 + kj] = kr[0];
        Ks[cur][(kkey + 32) * 12 + kj] = kr[1];
        Vs[cur][vd * 20 + vj] = vr[0];
        Vs[cur][(vd + 16) * 20 + vj] = vr[1];

        if (tile < 31) {
            size_t kt = (size_t)(tile + 1) * 64;
            size_t vt = (size_t)(tile + 1) * 512;
            kr[0] = KpB[(kt + kkey) * 8 + kj];
            kr[1] = KpB[(kt + kkey + 32) * 8 + kj];
            vr[0] = VpB[vt + (size_t)vd * 16 + vj];
            vr[1] = VpB[vt + (size_t)(vd + 16) * 16 + vj];
        }
        __syncthreads();

        float c[8][4] = {};
        #pragma unroll
        for (int nt = 0; nt < 8; nt++) {
            int key = nt * 8 + lq;
            #pragma unroll
            for (int kc = 0; kc < 2; kc++) {
                uint4 kv = Ks[cur][key * 12 + kc * 4 + lr];
                uint32_t bhf[2] = { kv.x, kv.y };
                uint32_t blf[2] = { kv.z, kv.w };
                mma16816(c[nt], qh[kc], bhf);
                mma16816(c[nt], qh[kc], blf);
                mma16816(c[nt], ql[kc], bhf);
            }
        }

        float mx0 = -1e30f, mx1 = -1e30f;
        #pragma unroll
        for (int nt = 0; nt < 8; nt++) {
            mx0 = fmaxf(mx0, fmaxf(c[nt][0], c[nt][1]));
            mx1 = fmaxf(mx1, fmaxf(c[nt][2], c[nt][3]));
        }
        mx0 = fmaxf(mx0, __shfl_xor_sync(0xffffffff, mx0, 1));
        mx0 = fmaxf(mx0, __shfl_xor_sync(0xffffffff, mx0, 2));
        mx1 = fmaxf(mx1, __shfl_xor_sync(0xffffffff, mx1, 1));
        mx1 = fmaxf(mx1, __shfl_xor_sync(0xffffffff, mx1, 2));
        float nm0 = fmaxf(m0, mx0), nm1 = fmaxf(m1, mx1);
        float f0 = exp2f(m0 - nm0), f1 = exp2f(m1 - nm1);
        m0 = nm0; m1 = nm1;
        l0 *= f0; l1 *= f1;
        #pragma unroll
        for (int dt = 0; dt < 4; dt++) {
            o[dt][0] *= f0; o[dt][1] *= f0;
            o[dt][2] *= f1; o[dt][3] *= f1;
        }
        #pragma unroll
        for (int nt = 0; nt < 8; nt++) {
            c[nt][0] = exp2f(c[nt][0] - m0);
            c[nt][1] = exp2f(c[nt][1] - m0);
            c[nt][2] = exp2f(c[nt][2] - m1);
            c[nt][3] = exp2f(c[nt][3] - m1);
            l0 += c[nt][0] + c[nt][1];
            l1 += c[nt][2] + c[nt][3];
        }

        #pragma unroll
        for (int kc = 0; kc < 4; kc++) {
            uint32_t ah[4], al[4];
            split2(c[2*kc][0],   c[2*kc][1],   ah[0], al[0]);
            split2(c[2*kc][2],   c[2*kc][3],   ah[1], al[1]);
            split2(c[2*kc+1][0], c[2*kc+1][1], ah[2], al[2]);
            split2(c[2*kc+1][2], c[2*kc+1][3], ah[3], al[3]);
            #pragma unroll
            for (int dt = 0; dt < 4; dt++) {
                int d = dt * 8 + lq;
                uint4 vv = Vs[cur][d * 20 + kc * 4 + lr];
                uint32_t bhf[2] = { vv.x, vv.y };
                uint32_t blf[2] = { vv.z, vv.w };
                mma16816(o[dt], ah, bhf);
                mma16816(o[dt], ah, blf);
                mma16816(o[dt], al, bhf);
            }
        }
    }

    l0 += __shfl_xor_sync(0xffffffff, l0, 1);
    l0 += __shfl_xor_sync(0xffffffff, l0, 2);
    l1 += __shfl_xor_sync(0xffffffff, l1, 1);
    l1 += __shfl_xor_sync(0xffffffff, l1, 2);
    float inv0 = 1.0f / l0, inv1 = 1.0f / l1;
    int b = bh >> 2, hh = bh & 3;
    size_t r0 = (size_t)(b * TT + row0) * 32;
    size_t r1 = (size_t)(b * TT + row0 + 8) * 32;
    uint32_t h0[4], l0a[4], h1[4], l1a[4];
    #pragma unroll
    for (int dt = 0; dt < 4; dt++) {
        split2(o[dt][0] * inv0, o[dt][1] * inv0, h0[dt], l0a[dt]);
        split2(o[dt][2] * inv1, o[dt][3] * inv1, h1[dt], l1a[dt]);
    }
    Cp[r0 + hh * 8 + lr]     = make_uint4(h0[0], h0[1], l0a[0], l0a[1]);
    Cp[r0 + hh * 8 + 4 + lr] = make_uint4(h0[2], h0[3], l0a[2], l0a[3]);
    Cp[r1 + hh * 8 + lr]     = make_uint4(h1[0], h1[1], l1a[0], l1a[1]);
    Cp[r1 + hh * 8 + 4 + lr] = make_uint4(h1[2], h1[3], l1a[2], l1a[3]);
}

// -------------------- launch ------------------------------------------------------
extern "C" void kernel_launch(void* const* d_in, const int* in_sizes, int n_in,
                              void* d_out, int out_size) {
    const float* in  = (const float*)d_in[0];
    const float* Wq  = (const float*)d_in[1];
    const float* bq  = (const float*)d_in[2];
    const float* Wk  = (const float*)d_in[3];
    const float* bk  = (const float*)d_in[4];
    const float* Wv  = (const float*)d_in[5];
    const float* bv  = (const float*)d_in[6];
    const float* Wo  = (const float*)d_in[7];
    const float* bo  = (const float*)d_in[8];
    const float* W1  = (const float*)d_in[9];
    const float* b1  = (const float*)d_in[10];
    const float* W2  = (const float*)d_in[11];
    const float* b2  = (const float*)d_in[12];
    const float* lng = (const float*)d_in[13];
    const float* lnb = (const float*)d_in[14];
    float* out = (float*)d_out;

    float* pe;
    uint4 *hnp, *ctxp, *qp, *kp, *vp, *wp;
    cudaGetSymbolAddress((void**)&pe,   g_pe);
    cudaGetSymbolAddress((void**)&hnp,  g_hnp);
    cudaGetSymbolAddress((void**)&ctxp, g_ctxp);
    cudaGetSymbolAddress((void**)&qp,   g_qp);
    cudaGetSymbolAddress((void**)&kp,   g_kp);
    cudaGetSymbolAddress((void**)&vp,   g_vp);
    cudaGetSymbolAddress((void**)&wp,   g_wp);

    pe_kernel<<<128, 256>>>(pe);
    wsplit_kernel<<<dim3(32, 6), 256>>>(Wq, Wk, Wv, Wo, W1, W2, wp);
    addpos_ln_kernel<<<ROWS / 8, 256>>>(in, pe, lng, lnb, hnp);

    for (int i = 0; i < NB; i++) {
        const uint4* Wpq = wp + (size_t)(0 * NB + i) * 4096;
        const uint4* Wpk = wp + (size_t)(1 * NB + i) * 4096;
        const uint4* Wpv = wp + (size_t)(2 * NB + i) * 4096;
        const uint4* Wpo = wp + (size_t)(3 * NB + i) * 4096;
        const uint4* Wp1 = wp + (size_t)(4 * NB + i) * 4096;
        const uint4* Wp2 = wp + (size_t)(5 * NB + i) * 4096;
        const float* bqi = bq + i * DD;
        const float* bki = bk + i * DD;
        const float* bvi = bv + i * DD;
        const float* boi = bo + i * DD;
        const float* b1i = b1 + i * DD;
        const float* b2i = b2 + i * DD;

        qkv64_kernel<<<dim3(256, 3), 256>>>(hnp, Wpq, bqi, Wpk, bki, Wpv, bvi,
                                            qp, kp, vp);
        attn_kernel<<<256, 256>>>(qp, kp, vp, ctxp);
        gemm_ln_kernel<<<512, 128>>>(ctxp, Wpo, boi,
                                     lng + (2 * i + 1) * DD, lnb + (2 * i + 1) * DD, hnp);
        if (i == NB - 1) {
            ffn_kernel<7><<<512, 128>>>(hnp, Wp1, b1i, Wp2, b2i,
                                        lng + 3 * DD, lnb + 3 * DD, out, nullptr);
        } else {
            ffn_kernel<6><<<512, 128>>>(hnp, Wp1, b1i, Wp2, b2i,
                                        lng + (2 * i + 2) * DD, lnb + (2 * i + 2) * DD,
                                        nullptr, hnp);
        }
    }
}

// round 17
// speedup vs baseline: 1.0213x; 1.0213x over previous
#include <cuda_runtime.h>
#include <cuda_bf16.h>
#include <stdint.h>
#include <math.h>

#define NB 2
#define BB 4
#define TT 2048
#define DD 128
#define HH 4
#define DK 32
#define ROWS (BB*TT)          // 8192
#define LN_EPS 1e-3f

// -------------------- scratch (device globals; no allocs allowed) ------------
__device__ float g_pe [TT*DD];
// packed activations: [row][kc(8)*4+lr(4)] uint4 = {hi(dp),hi(dp+4),lo(dp),lo(dp+4)}
__device__ uint4 g_hnp [ROWS*32];
__device__ uint4 g_ctxp[ROWS*32];
// packed Q/K: [bh=16][t=2048][kc(2)*4+lr(4)]
__device__ uint4 g_qp[32768*8];
__device__ uint4 g_kp[32768*8];
// packed V: [bh=16][tile(32)][d(32)][kc(4)*4+lr(4)] over key-pairs
__device__ uint4 g_vp[16*32*32*16];
// packed W: [matrix(12)][n(128)][kc(8)*4+lr(4)]
__device__ uint4 g_wp[12*128*32];

// -------------------- split-bf16 helpers ---------------------------------------
__device__ __forceinline__ uint32_t pk_bf2(float a, float b) {
    __nv_bfloat162 t = __floats2bfloat162_rn(a, b);
    return *reinterpret_cast<uint32_t*>(&t);
}
__device__ __forceinline__ void split2(float a, float b, uint32_t& h, uint32_t& l) {
    float ah = __bfloat162float(__float2bfloat16(a));
    float bh = __bfloat162float(__float2bfloat16(b));
    h = pk_bf2(ah, bh);
    l = pk_bf2(a - ah, b - bh);
}
__device__ __forceinline__ float2 unsplit(uint32_t h, uint32_t l) {
    __nv_bfloat162 hb = *reinterpret_cast<__nv_bfloat162*>(&h);
    __nv_bfloat162 lb = *reinterpret_cast<__nv_bfloat162*>(&l);
    return make_float2(__bfloat162float(hb.x) + __bfloat162float(lb.x),
                       __bfloat162float(hb.y) + __bfloat162float(lb.y));
}
__device__ __forceinline__ void mma16816(float c[4], const uint32_t a[4], const uint32_t b[2]) {
    asm volatile(
        "mma.sync.aligned.m16n8k16.row.col.f32.bf16.bf16.f32 "
        "{%0,%1,%2,%3}, {%4,%5,%6,%7}, {%8,%9}, {%0,%1,%2,%3};\n"
        : "+f"(c[0]), "+f"(c[1]), "+f"(c[2]), "+f"(c[3])
        : "r"(a[0]), "r"(a[1]), "r"(a[2]), "r"(a[3]), "r"(b[0]), "r"(b[1]));
}

// -------------------- positional encoding -------------------------------------
__global__ void pe_kernel(float* __restrict__ pe) {
    int i = blockIdx.x;
    double f = exp(-((double)(2 * i) / 128.0) * 9.210340371976184);
    const double TWO_PI = 6.283185307179586;
    const double INV_TWO_PI = 0.15915494309189535;
    for (int t = threadIdx.x; t < TT; t += blockDim.x) {
        double ang = (double)t * f;
        double r = ang - TWO_PI * floor(ang * INV_TWO_PI);
        float rf = (float)r;
        pe[t * DD + i] = (i & 1) ? cosf(rf) : sinf(rf);
    }
}

// -------------------- fused addpos + first LayerNorm -> packed hn ----------------
__global__ void addpos_ln_kernel(const float* __restrict__ in, const float* __restrict__ pe,
                                 const float* __restrict__ g, const float* __restrict__ b,
                                 uint4* __restrict__ Cp) {
    int row  = blockIdx.x * 8 + (threadIdx.x >> 5);
    int j    = threadIdx.x & 31;
    int dp   = ((j >> 2) << 3) + (j & 3);
    int d0   = 2 * dp;
    int t = row & (TT - 1);
    const float* inr = in + (size_t)row * 128;
    const float* per = pe + (size_t)t * 128;
    float2 xa = *(const float2*)&inr[d0];
    float2 xb = *(const float2*)&inr[d0 + 8];
    float2 pa = *(const float2*)&per[d0];
    float2 pb = *(const float2*)&per[d0 + 8];
    xa.x += pa.x; xa.y += pa.y; xb.x += pb.x; xb.y += pb.y;
    float s = xa.x + xa.y + xb.x + xb.y;
    #pragma unroll
    for (int o = 16; o > 0; o >>= 1) s += __shfl_xor_sync(0xffffffff, s, o);
    float mu = s * (1.0f / 128.0f);
    float dx0 = xa.x - mu, dx1 = xa.y - mu, dx2 = xb.x - mu, dx3 = xb.y - mu;
    float sq = dx0*dx0 + dx1*dx1 + dx2*dx2 + dx3*dx3;
    #pragma unroll
    for (int o = 16; o > 0; o >>= 1) sq += __shfl_xor_sync(0xffffffff, sq, o);
    float var = sq * (1.0f / 128.0f);
    float r = rsqrtf(var + LN_EPS);
    float2 ga = *(const float2*)&g[d0];
    float2 gb = *(const float2*)&g[d0 + 8];
    float2 ba = *(const float2*)&b[d0];
    float2 bb = *(const float2*)&b[d0 + 8];
    float y0 = ga.x * dx0 * r + ba.x;
    float y1 = ga.y * dx1 * r + ba.y;
    float y2 = gb.x * dx2 * r + bb.x;
    float y3 = gb.y * dx3 * r + bb.y;
    uint32_t h0, l0, h1, l1;
    split2(y0, y1, h0, l0);
    split2(y2, y3, h1, l1);
    Cp[(size_t)row * 32 + j] = make_uint4(h0, h1, l0, l1);
}

// -------------------- weight pre-split into packed uint4 -------------------------
__global__ void wsplit_kernel(const float* __restrict__ Wq, const float* __restrict__ Wk,
                              const float* __restrict__ Wv, const float* __restrict__ Wo,
                              const float* __restrict__ W1, const float* __restrict__ W2,
                              uint4* __restrict__ wp) {
    const float* Ws[6] = {Wq, Wk, Wv, Wo, W1, W2};
    int fam = blockIdx.y;
    int idx = blockIdx.x * 256 + threadIdx.x;   // 0..8191 = NB*128*32
    int layer = idx >> 12;
    int rem = idx & 4095;
    int n = rem >> 5;
    int j = rem & 31;
    int kc = j >> 2, lr = j & 3;
    int kp1 = kc * 8 + lr, kp2 = kp1 + 4;
    const float* Wm = Ws[fam] + layer * 128 * 128;
    uint32_t h1, l1, h2, l2;
    split2(Wm[(2 * kp1) * 128 + n], Wm[(2 * kp1 + 1) * 128 + n], h1, l1);
    split2(Wm[(2 * kp2) * 128 + n], Wm[(2 * kp2 + 1) * 128 + n], h2, l2);
    wp[((fam * NB + layer) * 128 + n) * 32 + j] = make_uint4(h1, h2, l1, l2);
}

// ==================== fused QKV (N=64 tile) =======================================
__global__ __launch_bounds__(256) void qkv64_kernel(
        const uint4* __restrict__ Ap,
        const uint4* __restrict__ Wpq, const float* __restrict__ bq,
        const uint4* __restrict__ Wpk, const float* __restrict__ bk,
        const uint4* __restrict__ Wpv, const float* __restrict__ bv,
        uint4* __restrict__ qp, uint4* __restrict__ kp, uint4* __restrict__ vp) {
    __shared__ __align__(16) float Vt[64 * 65];   // V transpose scratch only
    int tid = threadIdx.x;
    int w = tid >> 5, lane = tid & 31;
    int lq = lane >> 2, lr = lane & 3;
    int rg = w >> 1, cg = w & 1;
    int m0 = (blockIdx.x >> 1) * 64;
    int n0 = (blockIdx.x & 1) * 64;
    int sel = blockIdx.y;
    const float QSCL = 0.17677669529663687f * 1.4426950408889634f;
    const uint4* Wp = (sel == 0) ? Wpq : (sel == 1) ? Wpk : Wpv;
    const float* bias = (sel == 0) ? bq : (sel == 1) ? bk : bv;
    float scl = (sel == 0) ? QSCL : 1.0f;
    const uint4* Wb = Wp + (size_t)n0 * 32;

    int mrow = m0 + rg * 16 + lq;
    const uint4* A0 = Ap + (size_t)mrow * 32;
    const uint4* A1 = Ap + (size_t)(mrow + 8) * 32;
    float acc[4][4] = {};

    #pragma unroll
    for (int kc = 0; kc < 8; kc++) {
        uint4 a0 = A0[kc * 4 + lr];
        uint4 a1 = A1[kc * 4 + lr];
        uint32_t ah[4] = { a0.x, a1.x, a0.y, a1.y };
        uint32_t al[4] = { a0.z, a1.z, a0.w, a1.w };
        #pragma unroll
        for (int nt = 0; nt < 4; nt++) {
            int n = cg * 32 + nt * 8 + lq;
            uint4 wv = Wb[(size_t)n * 32 + kc * 4 + lr];
            uint32_t bh2[2] = { wv.x, wv.y };
            uint32_t bl2[2] = { wv.z, wv.w };
            mma16816(acc[nt], ah, bh2);
            mma16816(acc[nt], ah, bl2);
            mma16816(acc[nt], al, bh2);
        }
    }

    if (sel == 2) {
        int k0 = rg * 16 + lq;
        #pragma unroll
        for (int nt = 0; nt < 4; nt++) {
            int dc = cg * 32 + nt * 8 + 2 * lr;
            int n = n0 + dc;
            float2 bv2 = *(const float2*)&bias[n];
            Vt[dc * 65 + k0]           = acc[nt][0] + bv2.x;
            Vt[(dc + 1) * 65 + k0]     = acc[nt][1] + bv2.y;
            Vt[dc * 65 + k0 + 8]       = acc[nt][2] + bv2.x;
            Vt[(dc + 1) * 65 + k0 + 8] = acc[nt][3] + bv2.y;
        }
        __syncthreads();
        int b = m0 >> 11, tile = (m0 & 2047) >> 6;
        #pragma unroll
        for (int i = 0; i < 4; i++) {
            int idx = tid + i * 256;
            int dc = idx >> 4, j = idx & 15;
            int kc2 = j >> 2, lr2 = j & 3;
            int kpi = kc2 * 8 + lr2;
            float v0 = Vt[dc * 65 + 2 * kpi];
            float v1 = Vt[dc * 65 + 2 * kpi + 1];
            float v2 = Vt[dc * 65 + 2 * kpi + 8];
            float v3 = Vt[dc * 65 + 2 * kpi + 9];
            uint32_t h1, l1, h2, l2;
            split2(v0, v1, h1, l1);
            split2(v2, v3, h2, l2);
            int bh = (b << 2) + (n0 >> 5) + (dc >> 5);
            int d = dc & 31;
            vp[(((size_t)bh * 32 + tile) * 32 + d) * 16 + j] = make_uint4(h1, h2, l1, l2);
        }
        return;
    }

    uint4* Cp = (sel == 0) ? qp : kp;
    int hh = (n0 >> 5) + cg;
    int b0i = mrow >> 11, t0i = mrow & 2047;
    int b1i = (mrow + 8) >> 11, t1i = (mrow + 8) & 2047;
    uint32_t hi0[4], lo0r[4], hi1[4], lo1r[4];
    #pragma unroll
    for (int nt = 0; nt < 4; nt++) {
        int n = n0 + cg * 32 + nt * 8 + 2 * lr;
        float2 bv2 = *(const float2*)&bias[n];
        split2((acc[nt][0] + bv2.x) * scl, (acc[nt][1] + bv2.y) * scl, hi0[nt], lo0r[nt]);
        split2((acc[nt][2] + bv2.x) * scl, (acc[nt][3] + bv2.y) * scl, hi1[nt], lo1r[nt]);
    }
    size_t base0 = ((size_t)((b0i << 2) + hh) * 2048 + t0i) * 8;
    size_t base1 = ((size_t)((b1i << 2) + hh) * 2048 + t1i) * 8;
    Cp[base0 + lr]     = make_uint4(hi0[0], hi0[1], lo0r[0], lo0r[1]);
    Cp[base0 + 4 + lr] = make_uint4(hi0[2], hi0[3], lo0r[2], lo0r[3]);
    Cp[base1 + lr]     = make_uint4(hi1[0], hi1[1], lo1r[0], lo1r[1]);
    Cp[base1 + 4 + lr] = make_uint4(hi1[2], hi1[3], lo1r[2], lo1r[3]);
}

// ==================== fused layer tail: Wo+LN, W1+relu, W2+res+LN =================
// one block = 32 rows, 8 warps (rg=w>>2 rows, cg=w&3 cols), 3 chained GEMMs.
// MODE 6: -> packed Cp (next hn); MODE 7: -> fp32 C (final output)
template <int MODE>
__global__ __launch_bounds__(256) void tail_kernel(
        const uint4* __restrict__ Ap,                                      // ctx packed
        const uint4* __restrict__ Wpo, const float* __restrict__ bo,
        const uint4* __restrict__ Wp1, const float* __restrict__ b1,
        const uint4* __restrict__ Wp2, const float* __restrict__ b2,
        const float* __restrict__ lngm, const float* __restrict__ lnbm,    // mid LN (pre-FFN)
        const float* __restrict__ lngo, const float* __restrict__ lnbo,    // out LN
        float* __restrict__ C, uint4* __restrict__ Cp) {
    __shared__ __align__(16) uint4 Xp[32 * 36];   // x = LN(ctx@Wo+bo), packed
    __shared__ __align__(16) uint4 Tp[32 * 36];   // tmp = relu(x@W1+b1), packed
    __shared__ float ssum[32][4];
    __shared__ float ssq[32][4];
    int tid = threadIdx.x;
    int w = tid >> 5, lane = tid & 31;
    int lq = lane >> 2, lr = lane & 3;
    int rg = w >> 2, cg = w & 3;
    int m0 = blockIdx.x * 32;
    int lrow0 = rg * 16 + lq, lrow1 = lrow0 + 8;
    int mrow = m0 + lrow0;
    int jb = cg * 8 + lr;

    // ---- stage 0: x = LN(ctx @ Wo + bo) -> Xp (smem) ----
    {
        const uint4* A0 = Ap + (size_t)mrow * 32;
        const uint4* A1 = A0 + 8 * 32;
        float acc[4][4] = {};
        #pragma unroll
        for (int kc = 0; kc < 8; kc++) {
            uint4 a0 = A0[kc * 4 + lr];
            uint4 a1 = A1[kc * 4 + lr];
            uint32_t ah[4] = { a0.x, a1.x, a0.y, a1.y };
            uint32_t al[4] = { a0.z, a1.z, a0.w, a1.w };
            #pragma unroll
            for (int nt = 0; nt < 4; nt++) {
                int n = cg * 32 + nt * 8 + lq;
                uint4 wv = Wpo[(size_t)n * 32 + kc * 4 + lr];
                uint32_t bh2[2] = { wv.x, wv.y };
                uint32_t bl2[2] = { wv.z, wv.w };
                mma16816(acc[nt], ah, bh2);
                mma16816(acc[nt], ah, bl2);
                mma16816(acc[nt], al, bh2);
            }
        }
        float xs[4][4];
        #pragma unroll
        for (int nt = 0; nt < 4; nt++) {
            int n = cg * 32 + nt * 8 + 2 * lr;
            float2 bv = *(const float2*)&bo[n];
            xs[nt][0] = acc[nt][0] + bv.x;
            xs[nt][1] = acc[nt][1] + bv.y;
            xs[nt][2] = acc[nt][2] + bv.x;
            xs[nt][3] = acc[nt][3] + bv.y;
        }
        float sA = 0, qA = 0, sB = 0, qB = 0;
        #pragma unroll
        for (int nt = 0; nt < 4; nt++) {
            sA += xs[nt][0] + xs[nt][1];
            qA += xs[nt][0]*xs[nt][0] + xs[nt][1]*xs[nt][1];
            sB += xs[nt][2] + xs[nt][3];
            qB += xs[nt][2]*xs[nt][2] + xs[nt][3]*xs[nt][3];
        }
        #pragma unroll
        for (int o2 = 1; o2 < 4; o2 <<= 1) {
            sA += __shfl_xor_sync(0xffffffff, sA, o2);
            qA += __shfl_xor_sync(0xffffffff, qA, o2);
            sB += __shfl_xor_sync(0xffffffff, sB, o2);
            qB += __shfl_xor_sync(0xffffffff, qB, o2);
        }
        if (lr == 0) {
            ssum[lrow0][cg] = sA; ssq[lrow0][cg] = qA;
            ssum[lrow1][cg] = sB; ssq[lrow1][cg] = qB;
        }
        __syncthreads();
        float fsA = ssum[lrow0][0] + ssum[lrow0][1] + ssum[lrow0][2] + ssum[lrow0][3];
        float fqA = ssq[lrow0][0] + ssq[lrow0][1] + ssq[lrow0][2] + ssq[lrow0][3];
        float fsB = ssum[lrow1][0] + ssum[lrow1][1] + ssum[lrow1][2] + ssum[lrow1][3];
        float fqB = ssq[lrow1][0] + ssq[lrow1][1] + ssq[lrow1][2] + ssq[lrow1][3];
        float muA = fsA * (1.0f / 128.0f);
        float muB = fsB * (1.0f / 128.0f);
        float rA = rsqrtf(fqA * (1.0f / 128.0f) - muA * muA + LN_EPS);
        float rB = rsqrtf(fqB * (1.0f / 128.0f) - muB * muB + LN_EPS);
        uint32_t hA[4], lA[4], hB[4], lB[4];
        #pragma unroll
        for (int nt = 0; nt < 4; nt++) {
            int n = cg * 32 + nt * 8 + 2 * lr;
            float2 gv  = *(const float2*)&lngm[n];
            float2 bv2 = *(const float2*)&lnbm[n];
            split2(gv.x * (xs[nt][0] - muA) * rA + bv2.x,
                   gv.y * (xs[nt][1] - muA) * rA + bv2.y, hA[nt], lA[nt]);
            split2(gv.x * (xs[nt][2] - muB) * rB + bv2.x,
                   gv.y * (xs[nt][3] - muB) * rB + bv2.y, hB[nt], lB[nt]);
        }
        Xp[lrow0 * 36 + jb]     = make_uint4(hA[0], hA[1], lA[0], lA[1]);
        Xp[lrow0 * 36 + jb + 4] = make_uint4(hA[2], hA[3], lA[2], lA[3]);
        Xp[lrow1 * 36 + jb]     = make_uint4(hB[0], hB[1], lB[0], lB[1]);
        Xp[lrow1 * 36 + jb + 4] = make_uint4(hB[2], hB[3], lB[2], lB[3]);
    }
    __syncthreads();

    // ---- stage 1: tmp = relu(x @ W1 + b1) -> Tp (smem) ----
    {
        float acc[4][4] = {};
        #pragma unroll
        for (int kc = 0; kc < 8; kc++) {
            uint4 a0 = Xp[lrow0 * 36 + kc * 4 + lr];
            uint4 a1 = Xp[lrow1 * 36 + kc * 4 + lr];
            uint32_t ah[4] = { a0.x, a1.x, a0.y, a1.y };
            uint32_t al[4] = { a0.z, a1.z, a0.w, a1.w };
            #pragma unroll
            for (int nt = 0; nt < 4; nt++) {
                int n = cg * 32 + nt * 8 + lq;
                uint4 wv = Wp1[(size_t)n * 32 + kc * 4 + lr];
                uint32_t bh2[2] = { wv.x, wv.y };
                uint32_t bl2[2] = { wv.z, wv.w };
                mma16816(acc[nt], ah, bh2);
                mma16816(acc[nt], ah, bl2);
                mma16816(acc[nt], al, bh2);
            }
        }
        uint32_t h0[4], l0a[4], h1a[4], l1a[4];
        #pragma unroll
        for (int nt = 0; nt < 4; nt++) {
            int n = cg * 32 + nt * 8 + 2 * lr;
            float2 bv = *(const float2*)&b1[n];
            split2(fmaxf(acc[nt][0] + bv.x, 0.f), fmaxf(acc[nt][1] + bv.y, 0.f), h0[nt], l0a[nt]);
            split2(fmaxf(acc[nt][2] + bv.x, 0.f), fmaxf(acc[nt][3] + bv.y, 0.f), h1a[nt], l1a[nt]);
        }
        Tp[lrow0 * 36 + jb]     = make_uint4(h0[0], h0[1], l0a[0], l0a[1]);
        Tp[lrow0 * 36 + jb + 4] = make_uint4(h0[2], h0[3], l0a[2], l0a[3]);
        Tp[lrow1 * 36 + jb]     = make_uint4(h1a[0], h1a[1], l1a[0], l1a[1]);
        Tp[lrow1 * 36 + jb + 4] = make_uint4(h1a[2], h1a[3], l1a[2], l1a[3]);
    }
    __syncthreads();

    // ---- stage 2: y = LN(tmp @ W2 + b2 + x) ----
    float acc[4][4] = {};
    #pragma unroll
    for (int kc = 0; kc < 8; kc++) {
        uint4 a0 = Tp[lrow0 * 36 + kc * 4 + lr];
        uint4 a1 = Tp[lrow1 * 36 + kc * 4 + lr];
        uint32_t ah[4] = { a0.x, a1.x, a0.y, a1.y };
        uint32_t al[4] = { a0.z, a1.z, a0.w, a1.w };
        #pragma unroll
        for (int nt = 0; nt < 4; nt++) {
            int n = cg * 32 + nt * 8 + lq;
            uint4 wv = Wp2[(size_t)n * 32 + kc * 4 + lr];
            uint32_t bh2[2] = { wv.x, wv.y };
            uint32_t bl2[2] = { wv.z, wv.w };
            mma16816(acc[nt], ah, bh2);
            mma16816(acc[nt], ah, bl2);
            mma16816(acc[nt], al, bh2);
        }
    }

    float xs[4][4];
    {
        uint4 rA0 = Xp[lrow0 * 36 + jb];
        uint4 rA1 = Xp[lrow0 * 36 + jb + 4];
        uint4 rB0 = Xp[lrow1 * 36 + jb];
        uint4 rB1 = Xp[lrow1 * 36 + jb + 4];
        float2 r;
        r = unsplit(rA0.x, rA0.z); xs[0][0] = r.x; xs[0][1] = r.y;
        r = unsplit(rA0.y, rA0.w); xs[1][0] = r.x; xs[1][1] = r.y;
        r = unsplit(rA1.x, rA1.z); xs[2][0] = r.x; xs[2][1] = r.y;
        r = unsplit(rA1.y, rA1.w); xs[3][0] = r.x; xs[3][1] = r.y;
        r = unsplit(rB0.x, rB0.z); xs[0][2] = r.x; xs[0][3] = r.y;
        r = unsplit(rB0.y, rB0.w); xs[1][2] = r.x; xs[1][3] = r.y;
        r = unsplit(rB1.x, rB1.z); xs[2][2] = r.x; xs[2][3] = r.y;
        r = unsplit(rB1.y, rB1.w); xs[3][2] = r.x; xs[3][3] = r.y;
    }
    #pragma unroll
    for (int nt = 0; nt < 4; nt++) {
        int n = cg * 32 + nt * 8 + 2 * lr;
        float2 bv = *(const float2*)&b2[n];
        xs[nt][0] += acc[nt][0] + bv.x;
        xs[nt][1] += acc[nt][1] + bv.y;
        xs[nt][2] += acc[nt][2] + bv.x;
        xs[nt][3] += acc[nt][3] + bv.y;
    }
    float sA = 0, qA = 0, sB = 0, qB = 0;
    #pragma unroll
    for (int nt = 0; nt < 4; nt++) {
        sA += xs[nt][0] + xs[nt][1];
        qA += xs[nt][0]*xs[nt][0] + xs[nt][1]*xs[nt][1];
        sB += xs[nt][2] + xs[nt][3];
        qB += xs[nt][2]*xs[nt][2] + xs[nt][3]*xs[nt][3];
    }
    #pragma unroll
    for (int o2 = 1; o2 < 4; o2 <<= 1) {
        sA += __shfl_xor_sync(0xffffffff, sA, o2);
        qA += __shfl_xor_sync(0xffffffff, qA, o2);
        sB += __shfl_xor_sync(0xffffffff, sB, o2);
        qB += __shfl_xor_sync(0xffffffff, qB, o2);
    }
    __syncthreads();                 // ssum reuse: stage-0 reads done long ago, but be safe
    if (lr == 0) {
        ssum[lrow0][cg] = sA; ssq[lrow0][cg] = qA;
        ssum[lrow1][cg] = sB; ssq[lrow1][cg] = qB;
    }
    __syncthreads();
    float fsA = ssum[lrow0][0] + ssum[lrow0][1] + ssum[lrow0][2] + ssum[lrow0][3];
    float fqA = ssq[lrow0][0] + ssq[lrow0][1] + ssq[lrow0][2] + ssq[lrow0][3];
    float fsB = ssum[lrow1][0] + ssum[lrow1][1] + ssum[lrow1][2] + ssum[lrow1][3];
    float fqB = ssq[lrow1][0] + ssq[lrow1][1] + ssq[lrow1][2] + ssq[lrow1][3];
    float muA = fsA * (1.0f / 128.0f);
    float muB = fsB * (1.0f / 128.0f);
    float rA = rsqrtf(fqA * (1.0f / 128.0f) - muA * muA + LN_EPS);
    float rB = rsqrtf(fqB * (1.0f / 128.0f) - muB * muB + LN_EPS);
    float yA[4][2], yB[4][2];
    #pragma unroll
    for (int nt = 0; nt < 4; nt++) {
        int n = cg * 32 + nt * 8 + 2 * lr;
        float2 gv  = *(const float2*)&lngo[n];
        float2 bv2 = *(const float2*)&lnbo[n];
        yA[nt][0] = gv.x * (xs[nt][0] - muA) * rA + bv2.x;
        yA[nt][1] = gv.y * (xs[nt][1] - muA) * rA + bv2.y;
        yB[nt][0] = gv.x * (xs[nt][2] - muB) * rB + bv2.x;
        yB[nt][1] = gv.y * (xs[nt][3] - muB) * rB + bv2.y;
    }
    if (MODE == 7) {
        #pragma unroll
        for (int nt = 0; nt < 4; nt++) {
            int n = cg * 32 + nt * 8 + 2 * lr;
            *(float2*)&C[(size_t)mrow * 128 + n] = make_float2(yA[nt][0], yA[nt][1]);
            *(float2*)&C[(size_t)(mrow + 8) * 128 + n] = make_float2(yB[nt][0], yB[nt][1]);
        }
    } else {
        uint32_t hA[4], lA[4], hB[4], lB[4];
        #pragma unroll
        for (int nt = 0; nt < 4; nt++) {
            split2(yA[nt][0], yA[nt][1], hA[nt], lA[nt]);
            split2(yB[nt][0], yB[nt][1], hB[nt], lB[nt]);
        }
        Cp[(size_t)mrow * 32 + jb]           = make_uint4(hA[0], hA[1], lA[0], lA[1]);
        Cp[(size_t)mrow * 32 + jb + 4]       = make_uint4(hA[2], hA[3], lA[2], lA[3]);
        Cp[(size_t)(mrow + 8) * 32 + jb]     = make_uint4(hB[0], hB[1], lB[0], lB[1]);
        Cp[(size_t)(mrow + 8) * 32 + jb + 4] = make_uint4(hB[2], hB[3], lB[2], lB[3]);
    }
}

// -------------------- flash attention (packed uint4) -----------------------------
__global__ __launch_bounds__(256) void attn_kernel(
        const uint4* __restrict__ Qp, const uint4* __restrict__ Kp,
        const uint4* __restrict__ Vp, uint4* __restrict__ Cp) {
    __shared__ __align__(16) uint4 Ks[2][64 * 12];
    __shared__ __align__(16) uint4 Vs[2][32 * 20];

    int bid = blockIdx.x;
    int bh  = bid >> 4;
    int qc  = bid & 15;
    int q0  = qc * 128;
    int tid = threadIdx.x;
    int w    = tid >> 5;
    int lane = tid & 31;
    int lq   = lane >> 2;
    int lr   = lane & 3;
    int row0 = q0 + w * 16 + lq;

    const uint4* QpB = Qp + (size_t)bh * 2048 * 8;
    const uint4* KpB = Kp + (size_t)bh * 2048 * 8;
    const uint4* VpB = Vp + (size_t)bh * 32 * 512;

    uint32_t qh[2][4], ql[2][4];
    #pragma unroll
    for (int c2 = 0; c2 < 2; c2++) {
        uint4 a0 = QpB[(size_t)row0 * 8 + c2 * 4 + lr];
        uint4 a1 = QpB[(size_t)(row0 + 8) * 8 + c2 * 4 + lr];
        qh[c2][0] = a0.x; qh[c2][1] = a1.x; qh[c2][2] = a0.y; qh[c2][3] = a1.y;
        ql[c2][0] = a0.z; ql[c2][1] = a1.z; ql[c2][2] = a0.w; ql[c2][3] = a1.w;
    }

    float m0 = -1e30f, m1 = -1e30f, l0 = 0.f, l1 = 0.f;
    float o[4][4] = {};

    int kkey = tid >> 3, kj = tid & 7;
    int vd = tid >> 4, vj = tid & 15;
    uint4 kr[2], vr[2];
    kr[0] = KpB[(size_t)kkey * 8 + kj];
    kr[1] = KpB[(size_t)(kkey + 32) * 8 + kj];
    vr[0] = VpB[(size_t)vd * 16 + vj];
    vr[1] = VpB[(size_t)(vd + 16) * 16 + vj];

    for (int tile = 0; tile < 32; tile++) {
        int cur = tile & 1;
        Ks[cur][kkey * 12 + kj] = kr[0];
        Ks[cur][(kkey + 32) * 12 + kj] = kr[1];
        Vs[cur][vd * 20 + vj] = vr[0];
        Vs[cur][(vd + 16) * 20 + vj] = vr[1];

        if (tile < 31) {
            size_t kt = (size_t)(tile + 1) * 64;
            size_t vt = (size_t)(tile + 1) * 512;
            kr[0] = KpB[(kt + kkey) * 8 + kj];
            kr[1] = KpB[(kt + kkey + 32) * 8 + kj];
            vr[0] = VpB[vt + (size_t)vd * 16 + vj];
            vr[1] = VpB[vt + (size_t)(vd + 16) * 16 + vj];
        }
        __syncthreads();

        float c[8][4] = {};
        #pragma unroll
        for (int nt = 0; nt < 8; nt++) {
            int key = nt * 8 + lq;
            #pragma unroll
            for (int kc = 0; kc < 2; kc++) {
                uint4 kv = Ks[cur][key * 12 + kc * 4 + lr];
                uint32_t bhf[2] = { kv.x, kv.y };
                uint32_t blf[2] = { kv.z, kv.w };
                mma16816(c[nt], qh[kc], bhf);
                mma16816(c[nt], qh[kc], blf);
                mma16816(c[nt], ql[kc], bhf);
            }
        }

        float mx0 = -1e30f, mx1 = -1e30f;
        #pragma unroll
        for (int nt = 0; nt < 8; nt++) {
            mx0 = fmaxf(mx0, fmaxf(c[nt][0], c[nt][1]));
            mx1 = fmaxf(mx1, fmaxf(c[nt][2], c[nt][3]));
        }
        mx0 = fmaxf(mx0, __shfl_xor_sync(0xffffffff, mx0, 1));
        mx0 = fmaxf(mx0, __shfl_xor_sync(0xffffffff, mx0, 2));
        mx1 = fmaxf(mx1, __shfl_xor_sync(0xffffffff, mx1, 1));
        mx1 = fmaxf(mx1, __shfl_xor_sync(0xffffffff, mx1, 2));
        float nm0 = fmaxf(m0, mx0), nm1 = fmaxf(m1, mx1);
        float f0 = exp2f(m0 - nm0), f1 = exp2f(m1 - nm1);
        m0 = nm0; m1 = nm1;
        l0 *= f0; l1 *= f1;
        #pragma unroll
        for (int dt = 0; dt < 4; dt++) {
            o[dt][0] *= f0; o[dt][1] *= f0;
            o[dt][2] *= f1; o[dt][3] *= f1;
        }
        #pragma unroll
        for (int nt = 0; nt < 8; nt++) {
            c[nt][0] = exp2f(c[nt][0] - m0);
            c[nt][1] = exp2f(c[nt][1] - m0);
            c[nt][2] = exp2f(c[nt][2] - m1);
            c[nt][3] = exp2f(c[nt][3] - m1);
            l0 += c[nt][0] + c[nt][1];
            l1 += c[nt][2] + c[nt][3];
        }

        #pragma unroll
        for (int kc = 0; kc < 4; kc++) {
            uint32_t ah[4], al[4];
            split2(c[2*kc][0],   c[2*kc][1],   ah[0], al[0]);
            split2(c[2*kc][2],   c[2*kc][3],   ah[1], al[1]);
            split2(c[2*kc+1][0], c[2*kc+1][1], ah[2], al[2]);
            split2(c[2*kc+1][2], c[2*kc+1][3], ah[3], al[3]);
            #pragma unroll
            for (int dt = 0; dt < 4; dt++) {
                int d = dt * 8 + lq;
                uint4 vv = Vs[cur][d * 20 + kc * 4 + lr];
                uint32_t bhf[2] = { vv.x, vv.y };
                uint32_t blf[2] = { vv.z, vv.w };
                mma16816(o[dt], ah, bhf);
                mma16816(o[dt], ah, blf);
                mma16816(o[dt], al, bhf);
            }
        }
    }

    l0 += __shfl_xor_sync(0xffffffff, l0, 1);
    l0 += __shfl_xor_sync(0xffffffff, l0, 2);
    l1 += __shfl_xor_sync(0xffffffff, l1, 1);
    l1 += __shfl_xor_sync(0xffffffff, l1, 2);
    float inv0 = 1.0f / l0, inv1 = 1.0f / l1;
    int b = bh >> 2, hh = bh & 3;
    size_t r0 = (size_t)(b * TT + row0) * 32;
    size_t r1 = (size_t)(b * TT + row0 + 8) * 32;
    uint32_t h0[4], l0a[4], h1[4], l1a[4];
    #pragma unroll
    for (int dt = 0; dt < 4; dt++) {
        split2(o[dt][0] * inv0, o[dt][1] * inv0, h0[dt], l0a[dt]);
        split2(o[dt][2] * inv1, o[dt][3] * inv1, h1[dt], l1a[dt]);
    }
    Cp[r0 + hh * 8 + lr]     = make_uint4(h0[0], h0[1], l0a[0], l0a[1]);
    Cp[r0 + hh * 8 + 4 + lr] = make_uint4(h0[2], h0[3], l0a[2], l0a[3]);
    Cp[r1 + hh * 8 + lr]     = make_uint4(h1[0], h1[1], l1a[0], l1a[1]);
    Cp[r1 + hh * 8 + 4 + lr] = make_uint4(h1[2], h1[3], l1a[2], l1a[3]);
}

// -------------------- launch ------------------------------------------------------
extern "C" void kernel_launch(void* const* d_in, const int* in_sizes, int n_in,
                              void* d_out, int out_size) {
    const float* in  = (const float*)d_in[0];
    const float* Wq  = (const float*)d_in[1];
    const float* bq  = (const float*)d_in[2];
    const float* Wk  = (const float*)d_in[3];
    const float* bk  = (const float*)d_in[4];
    const float* Wv  = (const float*)d_in[5];
    const float* bv  = (const float*)d_in[6];
    const float* Wo  = (const float*)d_in[7];
    const float* bo  = (const float*)d_in[8];
    const float* W1  = (const float*)d_in[9];
    const float* b1  = (const float*)d_in[10];
    const float* W2  = (const float*)d_in[11];
    const float* b2  = (const float*)d_in[12];
    const float* lng = (const float*)d_in[13];
    const float* lnb = (const float*)d_in[14];
    float* out = (float*)d_out;

    float* pe;
    uint4 *hnp, *ctxp, *qp, *kp, *vp, *wp;
    cudaGetSymbolAddress((void**)&pe,   g_pe);
    cudaGetSymbolAddress((void**)&hnp,  g_hnp);
    cudaGetSymbolAddress((void**)&ctxp, g_ctxp);
    cudaGetSymbolAddress((void**)&qp,   g_qp);
    cudaGetSymbolAddress((void**)&kp,   g_kp);
    cudaGetSymbolAddress((void**)&vp,   g_vp);
    cudaGetSymbolAddress((void**)&wp,   g_wp);

    pe_kernel<<<128, 256>>>(pe);
    wsplit_kernel<<<dim3(32, 6), 256>>>(Wq, Wk, Wv, Wo, W1, W2, wp);
    addpos_ln_kernel<<<ROWS / 8, 256>>>(in, pe, lng, lnb, hnp);

    for (int i = 0; i < NB; i++) {
        const uint4* Wpq = wp + (size_t)(0 * NB + i) * 4096;
        const uint4* Wpk = wp + (size_t)(1 * NB + i) * 4096;
        const uint4* Wpv = wp + (size_t)(2 * NB + i) * 4096;
        const uint4* Wpo = wp + (size_t)(3 * NB + i) * 4096;
        const uint4* Wp1 = wp + (size_t)(4 * NB + i) * 4096;
        const uint4* Wp2 = wp + (size_t)(5 * NB + i) * 4096;
        const float* bqi = bq + i * DD;
        const float* bki = bk + i * DD;
        const float* bvi = bv + i * DD;
        const float* boi = bo + i * DD;
        const float* b1i = b1 + i * DD;
        const float* b2i = b2 + i * DD;

        qkv64_kernel<<<dim3(256, 3), 256>>>(hnp, Wpq, bqi, Wpk, bki, Wpv, bvi,
                                            qp, kp, vp);
        attn_kernel<<<256, 256>>>(qp, kp, vp, ctxp);
        const float* gm = lng + (2 * i + 1) * DD;
        const float* bm = lnb + (2 * i + 1) * DD;
        if (i == NB - 1) {
            tail_kernel<7><<<256, 256>>>(ctxp, Wpo, boi, Wp1, b1i, Wp2, b2i,
                                         gm, bm, lng + 3 * DD, lnb + 3 * DD,
                                         out, nullptr);
        } else {
            tail_kernel<6><<<256, 256>>>(ctxp, Wpo, boi, Wp1, b1i, Wp2, b2i,
                                         gm, bm, lng + (2 * i + 2) * DD, lnb + (2 * i + 2) * DD,
                                         nullptr, hnp);
        }
    }
}